// round 15
// baseline (speedup 1.0000x reference)
#include <cuda_runtime.h>
#include <cstdint>
#include <math.h>

#define Nn 8
#define Cc 64
#define Hh 256
#define Ww 256
#define HW (Hh*Ww)
#define PTS 8192
#define NB 256          // buckets: (n<<5) | (ph>>3)

// Scratch (__device__ globals per allocation rules; zero-initialized at load)
__device__ float g_x2t[(size_t)Nn * HW * Cc];
__device__ int g_cnt[NB];
__device__ int g_cur[NB];
__device__ int g_order[Nn * PTS];

// ---------------------------------------------------------------------------
// Kernel A: fused NCHW->NHWC transpose of x2 + out = (1+alpha)*x1 (proven
// 74.8us @ 80.7% DRAM) + point histogram (first 64 flat blocks, smem-reduced).
// ---------------------------------------------------------------------------
__global__ __launch_bounds__(256) void prep_kernel(
    const float4* __restrict__ x1, const float4* __restrict__ x2,
    const float* __restrict__ alpha, float4* __restrict__ out,
    const int2* __restrict__ SFL)
{
    __shared__ float tile[32][129];
    __shared__ int hist[NB];
    const int n   = blockIdx.z;
    const int c0  = blockIdx.y * 32;
    const int hw0 = blockIdx.x * 128;
    const float a1 = 1.0f + alpha[0];
    const int t = threadIdx.x;
    const int u = t & 7;
    const int j = t >> 3;
    const size_t base4 = (size_t)n * Cc * (HW / 4);

    // --- histogram: flat blocks 0..63 each cover 1024 points ---
    const int flat = (blockIdx.z * gridDim.y + blockIdx.y) * gridDim.x
                   + blockIdx.x;
    if (flat < 64) {
        hist[t] = 0;
        __syncthreads();
        #pragma unroll
        for (int it = 0; it < 4; it++) {
            int p = flat * 1024 + it * 256 + t;
            int2 sf = SFL[p];
            atomicAdd(&hist[((p / PTS) << 5) | (sf.x >> 3)], 1);
        }
        __syncthreads();
        if (hist[t]) atomicAdd(&g_cnt[t], hist[t]);
    }

    // --- transpose + elementwise ---
    #pragma unroll
    for (int m = 0; m < 4; m++) {
        int f4i = m * 8 + u;
        size_t idx = base4 + (size_t)(c0 + j) * (HW / 4) + (hw0 >> 2) + f4i;
        float4 v2 = x2[idx];
        float4 v1 = x1[idx];
        out[idx] = make_float4(a1 * v1.x, a1 * v1.y, a1 * v1.z, a1 * v1.w);
        tile[j][f4i * 4 + 0] = v2.x;
        tile[j][f4i * 4 + 1] = v2.y;
        tile[j][f4i * 4 + 2] = v2.z;
        tile[j][f4i * 4 + 3] = v2.w;
    }
    __syncthreads();

    float4* pt = (float4*)(g_x2t + (size_t)n * HW * Cc);
    #pragma unroll
    for (int v = 0; v < 4; v++) {
        int i = v * 32 + (t >> 3);
        float4 o;
        o.x = tile[4 * u + 0][i];
        o.y = tile[4 * u + 1][i];
        o.z = tile[4 * u + 2][i];
        o.w = tile[4 * u + 3][i];
        pt[(size_t)(hw0 + i) * (Cc / 4) + (c0 >> 2) + u] = o;
    }
}

// ---------------------------------------------------------------------------
// Scan: exclusive prefix of g_cnt -> g_cur; re-zero g_cnt for next replay.
// ---------------------------------------------------------------------------
__global__ __launch_bounds__(NB) void scan_kernel()
{
    __shared__ int s[NB];
    const int t = threadIdx.x;
    const int v = g_cnt[t];
    s[t] = v;
    __syncthreads();
    #pragma unroll
    for (int d = 1; d < NB; d <<= 1) {
        int x = (t >= d) ? s[t - d] : 0;
        __syncthreads();
        s[t] += x;
        __syncthreads();
    }
    g_cur[t] = s[t] - v;      // exclusive prefix
    g_cnt[t] = 0;             // ready for next iteration (first call: static 0)
}

// ---------------------------------------------------------------------------
// Scatter: place point indices into bucket-sorted order.
// ---------------------------------------------------------------------------
__global__ __launch_bounds__(1024) void scatter_kernel(const int2* __restrict__ SFL)
{
    int p = blockIdx.x * 1024 + threadIdx.x;
    int2 sf = SFL[p];
    int key = ((p / PTS) << 5) | (sf.x >> 3);
    int pos = atomicAdd(&g_cur[key], 1);
    g_order[pos] = p;
}

// reflect-pad index map for j = p + d - 2 in [-2, H+1]
__device__ __forceinline__ int refl(int j) {
    j = (j < 0) ? -j : j;
    return (j >= Hh) ? (2 * (Hh - 1) - j) : j;
}

// ---------------------------------------------------------------------------
// Kernel B: warp-per-point attention, consuming points in spatially-sorted
// order via g_order (L2/DRAM locality for gathers + scatters).
// Lane layout: half h = l>>4 owns pixels k = 2r+h; cg = 4*(l&15).
// ---------------------------------------------------------------------------
__global__ __launch_bounds__(256) void attn_kernel(
    const float* __restrict__ x1, const int2* __restrict__ SFL,
    const float* __restrict__ alpha, float* __restrict__ out)
{
    const int p = g_order[blockIdx.x * 8 + (threadIdx.x >> 5)];
    const int l = threadIdx.x & 31;
    const int n = p / PTS;
    const int2 sf = SFL[p];
    const int ph = sf.x, pw = sf.y;
    const int h  = l >> 4;
    const int cg = (l & 15) * 4;

    int hr[5], wr[5];
    #pragma unroll
    for (int d = 0; d < 5; d++) {
        hr[d] = refl(ph + d - 2);
        wr[d] = refl(pw + d - 2);
    }

    int offs[13];
    #pragma unroll
    for (int r = 0; r < 13; r++) {
        const int kA = 2 * r;
        const int kB = (2 * r + 1 <= 24) ? (2 * r + 1) : 24;
        int offA = (hr[kA / 5] * Ww + wr[kA % 5]) * Cc;
        int offB = (hr[kB / 5] * Ww + wr[kB % 5]) * Cc;
        offs[r] = h ? offB : offA;
    }

    const float* __restrict__ xt = g_x2t + (size_t)n * HW * Cc + cg;

    float4 xp = make_float4(0.f, 0.f, 0.f, 0.f);
    const size_t b0 = ((size_t)n * Cc + cg) * HW + (size_t)ph * Ww + pw;
    if (l < 16) {
        xp.x = x1[b0];
        xp.y = x1[b0 + HW];
        xp.z = x1[b0 + 2 * HW];
        xp.w = x1[b0 + 3 * HW];
    }
    xp.x += __shfl_xor_sync(0xffffffffu, xp.x, 16);
    xp.y += __shfl_xor_sync(0xffffffffu, xp.y, 16);
    xp.z += __shfl_xor_sync(0xffffffffu, xp.z, 16);
    xp.w += __shfl_xor_sync(0xffffffffu, xp.w, 16);

    // Pass A: energies, online softmax.
    float e[13];
    float m = -1e30f, sum = 0.f;
    #pragma unroll
    for (int r = 0; r < 13; r++) {
        const float4 a = *(const float4*)(xt + offs[r]);
        float s = xp.x * a.x + xp.y * a.y + xp.z * a.z + xp.w * a.w;
        s += __shfl_xor_sync(0xffffffffu, s, 1);
        s += __shfl_xor_sync(0xffffffffu, s, 2);
        s += __shfl_xor_sync(0xffffffffu, s, 4);
        s += __shfl_xor_sync(0xffffffffu, s, 8);
        float so = __shfl_xor_sync(0xffffffffu, s, 16);
        if (r == 12) {                 // k=25 doesn't exist
            if (h) s = -1e30f; else so = -1e30f;
        }
        e[r] = s;
        const float nm = fmaxf(m, fmaxf(s, so));
        sum = sum * __expf(m - nm) + __expf(s - nm) + __expf(so - nm);
        m = nm;
    }
    const float inv = 1.0f / sum;

    // Pass B: reload (L2-hot) and accumulate fusion.
    float4 f = make_float4(0.f, 0.f, 0.f, 0.f);
    #pragma unroll
    for (int r = 0; r < 13; r++) {
        const float4 a = *(const float4*)(xt + offs[r]);
        const float w = __expf(e[r] - m) * inv;
        f.x += w * a.x;
        f.y += w * a.y;
        f.z += w * a.z;
        f.w += w * a.w;
    }
    f.x += __shfl_xor_sync(0xffffffffu, f.x, 16);
    f.y += __shfl_xor_sync(0xffffffffu, f.y, 16);
    f.z += __shfl_xor_sync(0xffffffffu, f.z, 16);
    f.w += __shfl_xor_sync(0xffffffffu, f.w, 16);

    if (l < 16) {
        const float al = alpha[0];
        out[b0]          = xp.x + al * f.x;
        out[b0 + HW]     = xp.y + al * f.y;
        out[b0 + 2 * HW] = xp.z + al * f.z;
        out[b0 + 3 * HW] = xp.w + al * f.w;
    }
}

// ---------------------------------------------------------------------------
// SFL passthrough (int -> float, output dtype) at buffer tail.
// ---------------------------------------------------------------------------
__global__ void sfl_copy_kernel(const int* __restrict__ SFL,
                                float* __restrict__ dst, int n_elems)
{
    int i = blockIdx.x * blockDim.x + threadIdx.x;
    if (i < n_elems) dst[i] = (float)SFL[i];
}

extern "C" void kernel_launch(void* const* d_in, const int* in_sizes, int n_in,
                              void* d_out, int out_size)
{
    const float* x1    = (const float*)d_in[0];
    const float* x2    = (const float*)d_in[1];
    const int*   SFL   = (const int*)d_in[2];
    const float* alpha = (const float*)d_in[3];
    float* out = (float*)d_out;

    dim3 gA(HW / 128, Cc / 32, Nn);
    prep_kernel<<<gA, 256>>>((const float4*)x1, (const float4*)x2, alpha,
                             (float4*)out, (const int2*)SFL);

    scan_kernel<<<1, NB>>>();
    scatter_kernel<<<(Nn * PTS) / 1024, 1024>>>((const int2*)SFL);

    attn_kernel<<<(Nn * PTS) / 8, 256>>>(x1, (const int2*)SFL, alpha, out);

    const int nsfl = in_sizes[2];
    float* dst = out + ((size_t)out_size - (size_t)nsfl);
    sfl_copy_kernel<<<(nsfl + 255) / 256, 256>>>(SFL, dst, nsfl);
}

// round 16
// speedup vs baseline: 1.1927x; 1.1927x over previous
#include <cuda_runtime.h>
#include <cstdint>
#include <math.h>

#define Nn 8
#define Cc 64
#define Hh 256
#define Ww 256
#define HW (Hh*Ww)
#define PTS 8192

// NHWC-transposed copy of x2 (scratch; __device__ global per allocation rules)
__device__ float g_x2t[(size_t)Nn * HW * Cc];

// ---------------------------------------------------------------------------
// Kernel A: fused NCHW->NHWC transpose of x2 + out = (1+alpha)*x1, all float4.
// Proven 74.8us @ 80.7% DRAM — unchanged from R9.
// ---------------------------------------------------------------------------
__global__ __launch_bounds__(256) void prep_kernel(
    const float4* __restrict__ x1, const float4* __restrict__ x2,
    const float* __restrict__ alpha, float4* __restrict__ out)
{
    __shared__ float tile[32][129];
    const int n   = blockIdx.z;
    const int c0  = blockIdx.y * 32;
    const int hw0 = blockIdx.x * 128;
    const float a1 = 1.0f + alpha[0];
    const int t = threadIdx.x;
    const int u = t & 7;
    const int j = t >> 3;
    const size_t base4 = (size_t)n * Cc * (HW / 4);

    #pragma unroll
    for (int m = 0; m < 4; m++) {
        int f4i = m * 8 + u;
        size_t idx = base4 + (size_t)(c0 + j) * (HW / 4) + (hw0 >> 2) + f4i;
        float4 v2 = x2[idx];
        float4 v1 = x1[idx];
        out[idx] = make_float4(a1 * v1.x, a1 * v1.y, a1 * v1.z, a1 * v1.w);
        tile[j][f4i * 4 + 0] = v2.x;
        tile[j][f4i * 4 + 1] = v2.y;
        tile[j][f4i * 4 + 2] = v2.z;
        tile[j][f4i * 4 + 3] = v2.w;
    }
    __syncthreads();

    float4* pt = (float4*)(g_x2t + (size_t)n * HW * Cc);
    #pragma unroll
    for (int v = 0; v < 4; v++) {
        int i = v * 32 + (t >> 3);
        float4 o;
        o.x = tile[4 * u + 0][i];
        o.y = tile[4 * u + 1][i];
        o.z = tile[4 * u + 2][i];
        o.w = tile[4 * u + 3][i];
        pt[(size_t)(hw0 + i) * (Cc / 4) + (c0 >> 2) + u] = o;
    }
}

// reflect-pad index map for j = p + d - 2 in [-2, H+1]
__device__ __forceinline__ int refl(int j) {
    j = (j < 0) ? -j : j;
    return (j >= Hh) ? (2 * (Hh - 1) - j) : j;
}

// ---------------------------------------------------------------------------
// Kernel B: warp-per-point attention, FULLY-ONLINE single pass (flash-style
// rescaled accumulation). No a[13]/e[13]/offs[13] arrays -> ~45 live regs ->
// 5 blocks/SM (40 warps) for latency hiding. Lane layout: half h = l>>4 owns
// pixels k = 2r+h (r=0..12); channel group cg = 4*(l&15).
// Duplicate points write identical values -> benign race.
// ---------------------------------------------------------------------------
__global__ __launch_bounds__(256, 5) void attn_kernel(
    const float* __restrict__ x1, const int2* __restrict__ SFL,
    const float* __restrict__ alpha, float* __restrict__ out)
{
    const int p = blockIdx.x * 8 + (threadIdx.x >> 5);
    const int l = threadIdx.x & 31;
    const int n = p / PTS;
    const int2 sf = SFL[p];
    const int ph = sf.x, pw = sf.y;
    const int h  = l >> 4;
    const int cg = (l & 15) * 4;

    int hr[5], wr[5];
    #pragma unroll
    for (int d = 0; d < 5; d++) {
        hr[d] = refl(ph + d - 2);
        wr[d] = refl(pw + d - 2);
    }

    const float* __restrict__ xt = g_x2t + (size_t)n * HW * Cc + cg;

    // xp: lanes 0-15 load 4 scattered channels from x1, share to upper half.
    float4 xp = make_float4(0.f, 0.f, 0.f, 0.f);
    const size_t b0 = ((size_t)n * Cc + cg) * HW + (size_t)ph * Ww + pw;
    if (l < 16) {
        xp.x = x1[b0];
        xp.y = x1[b0 + HW];
        xp.z = x1[b0 + 2 * HW];
        xp.w = x1[b0 + 3 * HW];
    }
    xp.x += __shfl_xor_sync(0xffffffffu, xp.x, 16);
    xp.y += __shfl_xor_sync(0xffffffffu, xp.y, 16);
    xp.z += __shfl_xor_sync(0xffffffffu, xp.z, 16);
    xp.w += __shfl_xor_sync(0xffffffffu, xp.w, 16);

    // Online pass: running max m, running denom sum, rescaled numerator f.
    float m = -1e30f, sum = 0.f;
    float4 f = make_float4(0.f, 0.f, 0.f, 0.f);
    #pragma unroll
    for (int r = 0; r < 13; r++) {
        const int kA = 2 * r;
        const int kB = (2 * r + 1 <= 24) ? (2 * r + 1) : 24;  // alias, masked
        const int offA = (hr[kA / 5] * Ww + wr[kA % 5]) * Cc;
        const int offB = (hr[kB / 5] * Ww + wr[kB % 5]) * Cc;
        const float4 a = *(const float4*)(xt + (h ? offB : offA));

        float s = xp.x * a.x + xp.y * a.y + xp.z * a.z + xp.w * a.w;
        s += __shfl_xor_sync(0xffffffffu, s, 1);
        s += __shfl_xor_sync(0xffffffffu, s, 2);
        s += __shfl_xor_sync(0xffffffffu, s, 4);
        s += __shfl_xor_sync(0xffffffffu, s, 8);
        float so = __shfl_xor_sync(0xffffffffu, s, 16);
        if (r == 12) {                   // k=25 doesn't exist
            if (h) s = -1e30f; else so = -1e30f;
        }
        const float nm = fmaxf(m, fmaxf(s, so));
        const float c  = __expf(m - nm);   // rescale old accumulators
        const float w  = __expf(s - nm);   // own-half pixel weight
        sum = sum * c + w + __expf(so - nm);
        f.x = f.x * c + w * a.x;
        f.y = f.y * c + w * a.y;
        f.z = f.z * c + w * a.z;
        f.w = f.w * c + w * a.w;
        m = nm;
    }

    const float inv = 1.0f / sum;
    f.x *= inv; f.y *= inv; f.z *= inv; f.w *= inv;
    // Combine the two lane-halves (each accumulated its own pixels, same m-frame).
    f.x += __shfl_xor_sync(0xffffffffu, f.x, 16);
    f.y += __shfl_xor_sync(0xffffffffu, f.y, 16);
    f.z += __shfl_xor_sync(0xffffffffu, f.z, 16);
    f.w += __shfl_xor_sync(0xffffffffu, f.w, 16);

    if (l < 16) {
        const float al = alpha[0];
        out[b0]          = xp.x + al * f.x;
        out[b0 + HW]     = xp.y + al * f.y;
        out[b0 + 2 * HW] = xp.z + al * f.z;
        out[b0 + 3 * HW] = xp.w + al * f.w;
    }
}

// ---------------------------------------------------------------------------
// Kernel C: SFL passthrough (int -> float, output dtype) at buffer tail.
// ---------------------------------------------------------------------------
__global__ void sfl_copy_kernel(const int* __restrict__ SFL,
                                float* __restrict__ dst, int n_elems)
{
    int i = blockIdx.x * blockDim.x + threadIdx.x;
    if (i < n_elems) dst[i] = (float)SFL[i];
}

extern "C" void kernel_launch(void* const* d_in, const int* in_sizes, int n_in,
                              void* d_out, int out_size)
{
    const float* x1    = (const float*)d_in[0];
    const float* x2    = (const float*)d_in[1];
    const int*   SFL   = (const int*)d_in[2];
    const float* alpha = (const float*)d_in[3];
    float* out = (float*)d_out;

    dim3 gA(HW / 128, Cc / 32, Nn);
    prep_kernel<<<gA, 256>>>((const float4*)x1, (const float4*)x2, alpha,
                             (float4*)out);

    attn_kernel<<<(Nn * PTS) / 8, 256>>>(x1, (const int2*)SFL, alpha, out);

    const int nsfl = in_sizes[2];
    float* dst = out + ((size_t)out_size - (size_t)nsfl);
    sfl_copy_kernel<<<(nsfl + 255) / 256, 256>>>(SFL, dst, nsfl);
}